// round 15
// baseline (speedup 1.0000x reference)
#include <cuda_runtime.h>
#include <cuda_bf16.h>
#include <cuda_fp16.h>
#include <math.h>
#include <float.h>
#include <stdint.h>

// Problem constants
#define BB 2
#define TT 2048
#define EE 2048
#define HH 32
#define DD 64
#define RR 8
#define MTOT (BB * TT) /* 4096 */
#define SCALING 0.125f /* D^-0.5 */
#define LOG2E 1.4426950408889634f

// ---------------------------------------------------------------------------
// Scratch (device globals; no allocations allowed)
// ---------------------------------------------------------------------------
__device__ float g_U[4][MTOT * RR];
__device__ float g_colAlive[4][EE];
__device__ float g_rowAlive[4][EE];
// bf16 split operands for GEMMs
__device__ __nv_bfloat16 g_Wh[(size_t)4 * EE * EE];
__device__ __nv_bfloat16 g_Wl[(size_t)4 * EE * EE];
__device__ __nv_bfloat16 g_Xh[(size_t)MTOT * EE];   // hs split; later attn split
__device__ __nv_bfloat16 g_Xl[(size_t)MTOT * EE];
// Q/K/V fp16 hi/lo, all [B,H,T,D]
__device__ __half g_Qh[(size_t)BB * HH * TT * DD];
__device__ __half g_Ql[(size_t)BB * HH * TT * DD];
__device__ __half g_Kh[(size_t)BB * HH * TT * DD];
__device__ __half g_Kl[(size_t)BB * HH * TT * DD];
__device__ __half g_Vh[(size_t)BB * HH * TT * DD];
__device__ __half g_Vl[(size_t)BB * HH * TT * DD];

// ---------------------------------------------------------------------------
// PTX helpers (sm_80+ ISA only — harness compiles at sm_103 base, no tcgen05)
// ---------------------------------------------------------------------------
__device__ __forceinline__ uint32_t smem_u32(const void* p) {
    uint32_t a;
    asm("{ .reg .u64 t; cvta.to.shared.u64 t, %1; cvt.u32.u64 %0, t; }"
        : "=r"(a) : "l"(p));
    return a;
}
__device__ __forceinline__ void cp_async16(uint32_t dst, const void* src) {
    asm volatile("cp.async.cg.shared.global [%0], [%1], 16;"
                 :: "r"(dst), "l"(src) : "memory");
}
#define CP_COMMIT() asm volatile("cp.async.commit_group;" ::: "memory")
#define CP_WAIT1()  asm volatile("cp.async.wait_group 1;" ::: "memory")
#define CP_WAIT0()  asm volatile("cp.async.wait_group 0;" ::: "memory")

__device__ __forceinline__ void ldsm_x4(uint32_t r[4], uint32_t addr) {
    asm volatile("ldmatrix.sync.aligned.m8n8.x4.shared.b16 {%0,%1,%2,%3}, [%4];"
                 : "=r"(r[0]), "=r"(r[1]), "=r"(r[2]), "=r"(r[3]) : "r"(addr));
}
__device__ __forceinline__ void ldsm_t4(uint32_t r[4], uint32_t addr) {
    asm volatile("ldmatrix.sync.aligned.m8n8.x4.trans.shared.b16 {%0,%1,%2,%3}, [%4];"
                 : "=r"(r[0]), "=r"(r[1]), "=r"(r[2]), "=r"(r[3]) : "r"(addr));
}
__device__ __forceinline__ void mma16816(float c[4], const uint32_t a[4],
                                         uint32_t b0, uint32_t b1) {
    asm volatile(
        "mma.sync.aligned.m16n8k16.row.col.f32.bf16.bf16.f32 "
        "{%0,%1,%2,%3}, {%4,%5,%6,%7}, {%8,%9}, {%0,%1,%2,%3};"
        : "+f"(c[0]), "+f"(c[1]), "+f"(c[2]), "+f"(c[3])
        : "r"(a[0]), "r"(a[1]), "r"(a[2]), "r"(a[3]), "r"(b0), "r"(b1));
}
__device__ __forceinline__ void mma16816h(float c[4], const uint32_t a[4],
                                          uint32_t b0, uint32_t b1) {
    asm volatile(
        "mma.sync.aligned.m16n8k16.row.col.f32.f16.f16.f32 "
        "{%0,%1,%2,%3}, {%4,%5,%6,%7}, {%8,%9}, {%0,%1,%2,%3};"
        : "+f"(c[0]), "+f"(c[1]), "+f"(c[2]), "+f"(c[3])
        : "r"(a[0]), "r"(a[1]), "r"(a[2]), "r"(a[3]), "r"(b0), "r"(b1));
}
__device__ __forceinline__ uint32_t swz(uint32_t off) {
    return off ^ ((off >> 3) & 0x70);
}
__device__ __forceinline__ uint32_t packbf(float a, float b) {
    union { __nv_bfloat16 h[2]; uint32_t u; } t;
    t.h[0] = __float2bfloat16(a);
    t.h[1] = __float2bfloat16(b);
    return t.u;
}
__device__ __forceinline__ uint32_t packres(float a, float b, uint32_t hp) {
    union { __nv_bfloat16 h[2]; uint32_t u; } t;
    t.u = hp;
    return packbf(a - __bfloat162float(t.h[0]), b - __bfloat162float(t.h[1]));
}
// fp16 pack: a -> low half, b -> high half
__device__ __forceinline__ uint32_t packh(float a, float b) {
    uint32_t d;
    asm("cvt.rn.f16x2.f32 %0, %1, %2;" : "=r"(d) : "f"(b), "f"(a));
    return d;
}
__device__ __forceinline__ uint32_t packhres(float a, float b, uint32_t hp) {
    __half2 h = *reinterpret_cast<const __half2*>(&hp);
    return packh(a - __low2float(h), b - __high2float(h));
}
__device__ __forceinline__ uint32_t exp2h2(uint32_t y) {
    uint32_t p;
    asm volatile("ex2.approx.f16x2 %0, %1;" : "=r"(p) : "r"(y));
    return p;
}
__device__ __forceinline__ float exp2f32(float x) {
    float r;
    asm volatile("ex2.approx.f32 %0, %1;" : "=f"(r) : "f"(x));
    return r;
}
#define ONES_H2 0x3C003C00u

// ---------------------------------------------------------------------------
// Weight-mask ("alive") — early-exit scans
// ---------------------------------------------------------------------------
__global__ void alive2_kernel(const float* __restrict__ w0, const float* __restrict__ w1,
                              const float* __restrict__ w2, const float* __restrict__ w3) {
    const float* ws[4] = {w0, w1, w2, w3};
    const int p = blockIdx.y;
    const float* w = ws[p];
    const int idx = blockIdx.x * 256 + threadIdx.x;
    if (idx < EE) {
        float a = 0.0f;
        for (int i = 0; i < EE; i++)
            if (w[(size_t)i * EE + idx] != 0.0f) { a = 1.0f; break; }
        g_colAlive[p][idx] = a;
    } else {
        const int r = idx - EE;
        const float* row = w + (size_t)r * EE;
        float a = 0.0f;
        for (int j = 0; j < EE; j++)
            if (row[j] != 0.0f) { a = 1.0f; break; }
        g_rowAlive[p][r] = a;
    }
}

// ---------------------------------------------------------------------------
// fp32 -> (bf16 hi, bf16 lo) splits
// ---------------------------------------------------------------------------
__device__ __forceinline__ void split4(const float* __restrict__ src,
                                       __nv_bfloat16* __restrict__ hi,
                                       __nv_bfloat16* __restrict__ lo, int i) {
    float4 v = ((const float4*)src)[i];
    union { __nv_bfloat16 b[4]; uint2 u; } H, L;
    H.b[0] = __float2bfloat16(v.x);
    H.b[1] = __float2bfloat16(v.y);
    H.b[2] = __float2bfloat16(v.z);
    H.b[3] = __float2bfloat16(v.w);
    L.b[0] = __float2bfloat16(v.x - __bfloat162float(H.b[0]));
    L.b[1] = __float2bfloat16(v.y - __bfloat162float(H.b[1]));
    L.b[2] = __float2bfloat16(v.z - __bfloat162float(H.b[2]));
    L.b[3] = __float2bfloat16(v.w - __bfloat162float(H.b[3]));
    ((uint2*)hi)[i] = H.u;
    ((uint2*)lo)[i] = L.u;
}

// all 4 weights in one launch (blockIdx.y selects projection)
__global__ void splitw_kernel(const float* __restrict__ w0, const float* __restrict__ w1,
                              const float* __restrict__ w2, const float* __restrict__ w3) {
    const float* ws[4] = {w0, w1, w2, w3};
    const int p = blockIdx.y;
    const float* src = ws[p];
    __nv_bfloat16* hi = g_Wh + (size_t)p * EE * EE;
    __nv_bfloat16* lo = g_Wl + (size_t)p * EE * EE;
    const int n4 = EE * EE / 4;
    const int stride = gridDim.x * blockDim.x;
    for (int i = blockIdx.x * blockDim.x + threadIdx.x; i < n4; i += stride)
        split4(src, hi, lo, i);
}

__global__ void split_kernel(const float* __restrict__ src,
                             __nv_bfloat16* __restrict__ hi,
                             __nv_bfloat16* __restrict__ lo, int n4) {
    const int stride = gridDim.x * blockDim.x;
    for (int i = blockIdx.x * blockDim.x + threadIdx.x; i < n4; i += stride)
        split4(src, hi, lo, i);
}

// ---------------------------------------------------------------------------
// LoRA U kernels
// ---------------------------------------------------------------------------
__global__ __launch_bounds__(256) void u3_kernel(const float* __restrict__ X,
                                                 const float* __restrict__ L1a,
                                                 const float* __restrict__ L1b,
                                                 const float* __restrict__ L1c) {
    const int m = blockIdx.x;
    const int tid = threadIdx.x;
    float acc[3][RR];
#pragma unroll
    for (int p = 0; p < 3; p++)
#pragma unroll
        for (int r = 0; r < RR; r++) acc[p][r] = 0.0f;

    const float* Xr = X + (size_t)m * EE;
    for (int e = tid; e < EE; e += 256) {
        const float x = Xr[e];
        const float x0 = x * g_colAlive[0][e];
        const float x1 = x * g_colAlive[1][e];
        const float x2 = x * g_colAlive[2][e];
#pragma unroll
        for (int r = 0; r < RR; r++) {
            acc[0][r] = fmaf(x0, L1a[r * EE + e], acc[0][r]);
            acc[1][r] = fmaf(x1, L1b[r * EE + e], acc[1][r]);
            acc[2][r] = fmaf(x2, L1c[r * EE + e], acc[2][r]);
        }
    }
#pragma unroll
    for (int p = 0; p < 3; p++)
#pragma unroll
        for (int r = 0; r < RR; r++)
            for (int off = 16; off; off >>= 1)
                acc[p][r] += __shfl_xor_sync(0xffffffffu, acc[p][r], off);

    __shared__ float red[8][24];
    if ((tid & 31) == 0) {
        int w = tid >> 5;
#pragma unroll
        for (int p = 0; p < 3; p++)
#pragma unroll
            for (int r = 0; r < RR; r++) red[w][p * RR + r] = acc[p][r];
    }
    __syncthreads();
    if (tid < 24) {
        float s = 0.0f;
#pragma unroll
        for (int w = 0; w < 8; w++) s += red[w][tid];
        g_U[tid >> 3][m * RR + (tid & 7)] = s;
    }
}

__global__ __launch_bounds__(256) void uo_kernel(const __nv_bfloat16* __restrict__ Xh,
                                                 const __nv_bfloat16* __restrict__ Xl,
                                                 const float* __restrict__ L1) {
    const int m = blockIdx.x;
    const int tid = threadIdx.x;
    const float* ca = g_colAlive[3];
    float acc[RR];
#pragma unroll
    for (int r = 0; r < RR; r++) acc[r] = 0.0f;

    const __nv_bfloat16* Xhr = Xh + (size_t)m * EE;
    const __nv_bfloat16* Xlr = Xl + (size_t)m * EE;
    for (int e = tid; e < EE; e += 256) {
        float xv = (__bfloat162float(Xhr[e]) + __bfloat162float(Xlr[e])) * ca[e];
#pragma unroll
        for (int r = 0; r < RR; r++) acc[r] = fmaf(xv, L1[r * EE + e], acc[r]);
    }
#pragma unroll
    for (int r = 0; r < RR; r++)
        for (int off = 16; off; off >>= 1)
            acc[r] += __shfl_xor_sync(0xffffffffu, acc[r], off);

    __shared__ float red[8][RR];
    if ((tid & 31) == 0) {
        int w = tid >> 5;
#pragma unroll
        for (int r = 0; r < RR; r++) red[w][r] = acc[r];
    }
    __syncthreads();
    if (tid < RR) {
        float s = 0.0f;
#pragma unroll
        for (int w = 0; w < 8; w++) s += red[w][tid];
        g_U[3][m * RR + tid] = s;
    }
}

// ---------------------------------------------------------------------------
// Shared HMMA bf16-split GEMM core (Ah*Wh + Ah*Wl + Al*Wh)
// ---------------------------------------------------------------------------
#define STAGE_BYTES 65536
#define AH_OFF 0
#define AL_OFF 16384
#define WH_OFF 32768
#define WL_OFF 49152
#define GSMEM_TOTAL (2 * STAGE_BYTES)
#define NCHUNK (EE / 64)

__device__ __forceinline__ void stage_load(char* dst,
                                           const __nv_bfloat16* __restrict__ Ah,
                                           const __nv_bfloat16* __restrict__ Al,
                                           const __nv_bfloat16* __restrict__ Wh,
                                           const __nv_bfloat16* __restrict__ Wl,
                                           int m0, int n0, int k0, int tid) {
    const uint32_t dbase = smem_u32(dst);
#pragma unroll
    for (int i = 0; i < 4; i++) {
        int u = tid + i * 256;
        int row = u >> 3, c = u & 7;
        uint32_t so = swz((uint32_t)(row * 128 + c * 16));
        size_t goA = (size_t)(m0 + row) * EE + k0 + c * 8;
        size_t goW = (size_t)(n0 + row) * EE + k0 + c * 8;
        cp_async16(dbase + AH_OFF + so, Ah + goA);
        cp_async16(dbase + AL_OFF + so, Al + goA);
        cp_async16(dbase + WH_OFF + so, Wh + goW);
        cp_async16(dbase + WL_OFF + so, Wl + goW);
    }
}

__device__ __forceinline__ void gemm_core(float acc[4][4][4],
                                          const __nv_bfloat16* __restrict__ Ah,
                                          const __nv_bfloat16* __restrict__ Al,
                                          const __nv_bfloat16* __restrict__ Wh,
                                          const __nv_bfloat16* __restrict__ Wl,
                                          int m0, int n0, char* smem) {
    const int tid = threadIdx.x;
    const int wid = tid >> 5;
    const int lane = tid & 31;
    const int wm = wid & 1;
    const int wn = wid >> 1;
    const int arow = lane & 15;
    const int acolb = (lane >> 4) << 4;
    const int brow = (lane & 7) + ((lane >> 4) << 3);
    const int bcolb = ((lane >> 3) & 1) << 4;

    stage_load(smem, Ah, Al, Wh, Wl, m0, n0, 0, tid);
    CP_COMMIT();

    for (int ch = 0; ch < NCHUNK; ch++) {
        const int s = ch & 1;
        if (ch + 1 < NCHUNK) {
            stage_load(smem + (s ^ 1) * STAGE_BYTES, Ah, Al, Wh, Wl,
                       m0, n0, (ch + 1) * 64, tid);
            CP_COMMIT();
            CP_WAIT1();
        } else {
            CP_WAIT0();
        }
        __syncthreads();

        const uint32_t sb = smem_u32(smem + s * STAGE_BYTES);
#pragma unroll
        for (int kk = 0; kk < 4; kk++) {
            const int kB = kk * 32;
            uint32_t ah[4][4], al[4][4], bh[2][4], bl[2][4];
#pragma unroll
            for (int fm = 0; fm < 4; fm++) {
                uint32_t so = swz((uint32_t)((wm * 64 + fm * 16 + arow) * 128 + kB + acolb));
                ldsm_x4(ah[fm], sb + AH_OFF + so);
                ldsm_x4(al[fm], sb + AL_OFF + so);
            }
#pragma unroll
            for (int g = 0; g < 2; g++) {
                uint32_t so = swz((uint32_t)((wn * 32 + g * 16 + brow) * 128 + kB + bcolb));
                ldsm_x4(bh[g], sb + WH_OFF + so);
                ldsm_x4(bl[g], sb + WL_OFF + so);
            }
#pragma unroll
            for (int fm = 0; fm < 4; fm++)
#pragma unroll
                for (int fn = 0; fn < 4; fn++) {
                    const int g = fn >> 1, p = (fn & 1) << 1;
                    mma16816(acc[fm][fn], ah[fm], bh[g][p], bh[g][p + 1]);
                    mma16816(acc[fm][fn], ah[fm], bl[g][p], bl[g][p + 1]);
                    mma16816(acc[fm][fn], al[fm], bh[g][p], bh[g][p + 1]);
                }
        }
        __syncthreads();
    }
}

// ---------------------------------------------------------------------------
// Fused QKV GEMM: grid.z selects projection. All outputs fp16 hi/lo in
// head layout [B,H,T,D]. Q pre-scaled by SCALING*LOG2E.
// ---------------------------------------------------------------------------
struct QkvArgs {
    const __nv_bfloat16* Wh[3];
    const __nv_bfloat16* Wl[3];
    const float* bias[3];
    const float* U[3];
    const float* L2[3];
    const float* alive[3];
    uint16_t* OutH[3];
    uint16_t* OutL[3];
    float scale[3];
};

__global__ __launch_bounds__(256, 1) void qkv_hmma(
    const __nv_bfloat16* __restrict__ Ah, const __nv_bfloat16* __restrict__ Al,
    QkvArgs args) {
    extern __shared__ char smem[];
    const int z = blockIdx.z;
    const int m0 = blockIdx.y * 128;
    const int n0 = blockIdx.x * 128;
    const int tid = threadIdx.x;
    const int wid = tid >> 5;
    const int lane = tid & 31;
    const int wm = wid & 1;
    const int wn = wid >> 1;

    float acc[4][4][4];
#pragma unroll
    for (int a = 0; a < 4; a++)
#pragma unroll
        for (int b = 0; b < 4; b++)
#pragma unroll
            for (int c = 0; c < 4; c++) acc[a][b][c] = 0.0f;

    gemm_core(acc, Ah, Al, args.Wh[z], args.Wl[z], m0, n0, smem);

    const float* bias = args.bias[z];
    const float* U = args.U[z];
    const float* L2 = args.L2[z];
    const float* alive = args.alive[z];
    uint16_t* OutH = args.OutH[z];
    uint16_t* OutL = args.OutL[z];
    const float scale = args.scale[z];

#pragma unroll
    for (int fm = 0; fm < 4; fm++) {
        const int mlo = m0 + wm * 64 + fm * 16 + (lane >> 2);
        const int mhi = mlo + 8;
        float ulo[RR], uhi[RR];
#pragma unroll
        for (int r = 0; r < RR; r++) {
            ulo[r] = U[mlo * RR + r];
            uhi[r] = U[mhi * RR + r];
        }
#pragma unroll
        for (int fn = 0; fn < 4; fn++) {
            const int n = n0 + wn * 32 + fn * 8 + ((lane & 3) << 1);
            float out[4];
#pragma unroll
            for (int jj = 0; jj < 2; jj++) {
                const int nn = n + jj;
                const float av = alive[nn];
                float lo = acc[fm][fn][jj] + bias[nn];
                float hi = acc[fm][fn][2 + jj] + bias[nn];
#pragma unroll
                for (int r = 0; r < RR; r++) {
                    const float lv = L2[nn * RR + r] * av;
                    lo = fmaf(ulo[r], lv, lo);
                    hi = fmaf(uhi[r], lv, hi);
                }
                out[jj] = lo * scale;
                out[2 + jj] = hi * scale;
            }
            const int h = n >> 6, d0 = n & 63;
            const int blo = mlo >> 11, tlo = mlo & (TT - 1);
            const int bhi = mhi >> 11, thi = mhi & (TT - 1);
            size_t off_lo = ((size_t)(blo * HH + h) * TT + tlo) * DD + d0;
            size_t off_hi = ((size_t)(bhi * HH + h) * TT + thi) * DD + d0;
            uint32_t hp0 = packh(out[0], out[1]);
            uint32_t hp1 = packh(out[2], out[3]);
            *(uint32_t*)(OutH + off_lo) = hp0;
            *(uint32_t*)(OutL + off_lo) = packhres(out[0], out[1], hp0);
            *(uint32_t*)(OutH + off_hi) = hp1;
            *(uint32_t*)(OutL + off_hi) = packhres(out[2], out[3], hp1);
        }
    }
}

// ---------------------------------------------------------------------------
// O-projection GEMM (fp32 out, [M,E])
// ---------------------------------------------------------------------------
__global__ __launch_bounds__(256, 1) void gemm_out(
    const __nv_bfloat16* __restrict__ Ah, const __nv_bfloat16* __restrict__ Al,
    const __nv_bfloat16* __restrict__ Wh, const __nv_bfloat16* __restrict__ Wl,
    const float* __restrict__ bias, const float* __restrict__ U,
    const float* __restrict__ L2, const float* __restrict__ rowAlive,
    float* __restrict__ Cout) {
    extern __shared__ char smem[];
    const int tid = threadIdx.x;
    const int wid = tid >> 5;
    const int lane = tid & 31;
    const int wm = wid & 1;
    const int wn = wid >> 1;
    const int m0 = blockIdx.y * 128;
    const int n0 = blockIdx.x * 128;

    float acc[4][4][4];
#pragma unroll
    for (int a = 0; a < 4; a++)
#pragma unroll
        for (int b = 0; b < 4; b++)
#pragma unroll
            for (int c = 0; c < 4; c++) acc[a][b][c] = 0.0f;

    gemm_core(acc, Ah, Al, Wh, Wl, m0, n0, smem);

#pragma unroll
    for (int fm = 0; fm < 4; fm++) {
        const int mlo = m0 + wm * 64 + fm * 16 + (lane >> 2);
        const int mhi = mlo + 8;
        float ulo[RR], uhi[RR];
#pragma unroll
        for (int r = 0; r < RR; r++) {
            ulo[r] = U[mlo * RR + r];
            uhi[r] = U[mhi * RR + r];
        }
#pragma unroll
        for (int fn = 0; fn < 4; fn++) {
            const int n = n0 + wn * 32 + fn * 8 + ((lane & 3) << 1);
            float out[4];
#pragma unroll
            for (int jj = 0; jj < 2; jj++) {
                const int nn = n + jj;
                const float av = rowAlive[nn];
                float lo = acc[fm][fn][jj] + bias[nn];
                float hi = acc[fm][fn][2 + jj] + bias[nn];
#pragma unroll
                for (int r = 0; r < RR; r++) {
                    const float lv = L2[nn * RR + r] * av;
                    lo = fmaf(ulo[r], lv, lo);
                    hi = fmaf(uhi[r], lv, hi);
                }
                out[jj] = lo;
                out[2 + jj] = hi;
            }
            *(float2*)(Cout + (size_t)mlo * EE + n) = make_float2(out[0], out[1]);
            *(float2*)(Cout + (size_t)mhi * EE + n) = make_float2(out[2], out[3]);
        }
    }
}

// ---------------------------------------------------------------------------
// Flash attention: fp16 3-pass QK^T (QhKh + QhKl + QlKh; exact to 2^-22),
// Q pre-scaled (log2 domain), packed ex2.approx.f16x2 softmax, fp16 P,
// fp16-split 2-pass PV, row-sums via MMA with all-ones B. 128 threads.
// ---------------------------------------------------------------------------
#define FQ_H 0
#define FQ_L 8192
#define FSTG 16384
#define FK_H 0
#define FK_L 8192
#define FV_H 16384
#define FV_L 24576
#define FSTG_SZ 32768
#define FSMEM (16384 + 2 * FSTG_SZ)   /* 81920 */

__device__ __forceinline__ void f_load_tile(uint32_t dstb,
                                            const uint16_t* __restrict__ src,
                                            int tid) {
#pragma unroll
    for (int i = 0; i < 4; i++) {
        int u = tid + i * 128;
        int r = u >> 3, c = u & 7;
        cp_async16(dstb + swz((uint32_t)(r * 128 + c * 16)), src + r * 64 + c * 8);
    }
}

__global__ __launch_bounds__(128, 2) void flash_hmma() {
    const int qb = (TT / 64 - 1) - blockIdx.x;
    const int h = blockIdx.y;
    const int b = blockIdx.z;
    const int t0 = qb * 64;
    const size_t ho = (size_t)(b * HH + h) * TT * DD;

    extern __shared__ char smem[];
    const uint32_t sbase = smem_u32(smem);
    const int tid = threadIdx.x, wid = tid >> 5, lane = tid & 31;
    const int rq = lane >> 2, cq = lane & 3;

    f_load_tile(sbase + FQ_H, (const uint16_t*)(g_Qh + ho + (size_t)t0 * DD), tid);
    f_load_tile(sbase + FQ_L, (const uint16_t*)(g_Ql + ho + (size_t)t0 * DD), tid);
    f_load_tile(sbase + FSTG + FK_H, (const uint16_t*)(g_Kh + ho), tid);
    f_load_tile(sbase + FSTG + FK_L, (const uint16_t*)(g_Kl + ho), tid);
    f_load_tile(sbase + FSTG + FV_H, (const uint16_t*)(g_Vh + ho), tid);
    f_load_tile(sbase + FSTG + FV_L, (const uint16_t*)(g_Vl + ho), tid);
    CP_COMMIT();

    float oacc[8][4];
#pragma unroll
    for (int f = 0; f < 8; f++)
#pragma unroll
        for (int j = 0; j < 4; j++) oacc[f][j] = 0.0f;
    float m0 = -1e30f, m1 = -1e30f, l0 = 0.0f, l1 = 0.0f;

    const int arow = lane & 15;
    const int acolb = (lane >> 4) << 4;
    const int brow = (lane & 7) + ((lane >> 4) << 3);
    const int bcolb = ((lane >> 3) & 1) << 4;

    for (int kb = 0; kb <= qb; kb++) {
        const int s = kb & 1;
        if (kb < qb) {
            const uint32_t nb = sbase + FSTG + (s ^ 1) * FSTG_SZ;
            const size_t so = (size_t)(kb + 1) * 64 * DD;
            f_load_tile(nb + FK_H, (const uint16_t*)(g_Kh + ho + so), tid);
            f_load_tile(nb + FK_L, (const uint16_t*)(g_Kl + ho + so), tid);
            f_load_tile(nb + FV_H, (const uint16_t*)(g_Vh + ho + so), tid);
            f_load_tile(nb + FV_L, (const uint16_t*)(g_Vl + ho + so), tid);
            CP_COMMIT();
            CP_WAIT1();
        } else {
            CP_WAIT0();
        }
        __syncthreads();

        const uint32_t kvb = sbase + FSTG + s * FSTG_SZ;
        float sacc[8][4];
#pragma unroll
        for (int f = 0; f < 8; f++)
#pragma unroll
            for (int j = 0; j < 4; j++) sacc[f][j] = 0.0f;

        // S' = (Q*scale*log2e) K^T  (fp16 3-pass: QhKh + QhKl + QlKh)
#pragma unroll
        for (int kk = 0; kk < 4; kk++) {
            const int kB = kk * 32;
            uint32_t qh4[4], ql4[4];
            uint32_t qoff = swz((uint32_t)((wid * 16 + arow) * 128 + kB + acolb));
            ldsm_x4(qh4, sbase + FQ_H + qoff);
            ldsm_x4(ql4, sbase + FQ_L + qoff);
            uint32_t kh4[4][4], kl4[4][4];
#pragma unroll
            for (int g = 0; g < 4; g++) {
                uint32_t koff = swz((uint32_t)((g * 16 + brow) * 128 + kB + bcolb));
                ldsm_x4(kh4[g], kvb + FK_H + koff);
                ldsm_x4(kl4[g], kvb + FK_L + koff);
            }
#pragma unroll
            for (int fn = 0; fn < 8; fn++) {
                const int g = fn >> 1, p = (fn & 1) << 1;
                mma16816h(sacc[fn], qh4, kh4[g][p], kh4[g][p + 1]);
                mma16816h(sacc[fn], qh4, kl4[g][p], kl4[g][p + 1]);
                mma16816h(sacc[fn], ql4, kh4[g][p], kh4[g][p + 1]);
            }
        }

        if (kb == qb) {
            const int rlo = wid * 16 + rq, rhi = rlo + 8;
#pragma unroll
            for (int fn = 0; fn < 8; fn++) {
                const int col = fn * 8 + 2 * cq;
                if (col > rlo) sacc[fn][0] = -FLT_MAX;
                if (col + 1 > rlo) sacc[fn][1] = -FLT_MAX;
                if (col > rhi) sacc[fn][2] = -FLT_MAX;
                if (col + 1 > rhi) sacc[fn][3] = -FLT_MAX;
            }
        }

        // row max (log2 domain)
        float mx0 = -FLT_MAX, mx1 = -FLT_MAX;
#pragma unroll
        for (int fn = 0; fn < 8; fn++) {
            mx0 = fmaxf(mx0, fmaxf(sacc[fn][0], sacc[fn][1]));
            mx1 = fmaxf(mx1, fmaxf(sacc[fn][2], sacc[fn][3]));
        }
        mx0 = fmaxf(mx0, __shfl_xor_sync(0xffffffffu, mx0, 1));
        mx0 = fmaxf(mx0, __shfl_xor_sync(0xffffffffu, mx0, 2));
        mx1 = fmaxf(mx1, __shfl_xor_sync(0xffffffffu, mx1, 1));
        mx1 = fmaxf(mx1, __shfl_xor_sync(0xffffffffu, mx1, 2));
        const float nm0 = fmaxf(m0, mx0), nm1 = fmaxf(m1, mx1);
        const float c0 = exp2f32(m0 - nm0), c1 = exp2f32(m1 - nm1);
        m0 = nm0;
        m1 = nm1;

        // packed exp2 -> fp16 P frags
        uint32_t pf[4][4];
#pragma unroll
        for (int kk = 0; kk < 4; kk++) {
#pragma unroll
            for (int q = 0; q < 2; q++) {
                const int fn = 2 * kk + q;
                pf[kk][2 * q + 0] =
                    exp2h2(packh(sacc[fn][0] - nm0, sacc[fn][1] - nm0));
                pf[kk][2 * q + 1] =
                    exp2h2(packh(sacc[fn][2] - nm1, sacc[fn][3] - nm1));
            }
        }

        // row sums via MMA with all-ones B
        float lacc[4] = {0.0f, 0.0f, 0.0f, 0.0f};
#pragma unroll
        for (int kk = 0; kk < 4; kk++)
            mma16816h(lacc, pf[kk], ONES_H2, ONES_H2);
        l0 = l0 * c0 + lacc[0];
        l1 = l1 * c1 + lacc[2];
#pragma unroll
        for (int fn = 0; fn < 8; fn++) {
            oacc[fn][0] *= c0;
            oacc[fn][1] *= c0;
            oacc[fn][2] *= c1;
            oacc[fn][3] *= c1;
        }

        // O += P V (fp16, 2-pass split); V via trans ldmatrix
#pragma unroll
        for (int kk = 0; kk < 4; kk++) {
            const int vrow = kk * 16 + (lane & 15);
            const int vcolb = (lane >> 4) << 4;
            uint32_t vh4[4][4], vl4[4][4];
#pragma unroll
            for (int g = 0; g < 4; g++) {
                uint32_t voff = swz((uint32_t)(vrow * 128 + g * 32 + vcolb));
                ldsm_t4(vh4[g], kvb + FV_H + voff);
                ldsm_t4(vl4[g], kvb + FV_L + voff);
            }
#pragma unroll
            for (int fn = 0; fn < 8; fn++) {
                const int g = fn >> 1, p = (fn & 1) << 1;
                mma16816h(oacc[fn], pf[kk], vh4[g][p], vh4[g][p + 1]);
                mma16816h(oacc[fn], pf[kk], vl4[g][p], vl4[g][p + 1]);
            }
        }
        __syncthreads();
    }

    // Epilogue: normalize, split to bf16 hi/lo, write [B*T, E]
    const float i0 = 1.0f / l0, i1 = 1.0f / l1;
    const int tlo = t0 + wid * 16 + rq, thi = tlo + 8;
    const size_t rlo = ((size_t)(b * TT) + tlo) * EE + h * DD;
    const size_t rhi = ((size_t)(b * TT) + thi) * EE + h * DD;
#pragma unroll
    for (int fn = 0; fn < 8; fn++) {
        const int e = fn * 8 + 2 * cq;
        float v0 = oacc[fn][0] * i0, v1 = oacc[fn][1] * i0;
        float v2 = oacc[fn][2] * i1, v3 = oacc[fn][3] * i1;
        uint32_t hp0 = packbf(v0, v1);
        uint32_t hp1 = packbf(v2, v3);
        *(uint32_t*)(g_Xh + rlo + e) = hp0;
        *(uint32_t*)(g_Xl + rlo + e) = packres(v0, v1, hp0);
        *(uint32_t*)(g_Xh + rhi + e) = hp1;
        *(uint32_t*)(g_Xl + rhi + e) = packres(v2, v3, hp1);
    }
}

// ---------------------------------------------------------------------------
// Launch
// ---------------------------------------------------------------------------
extern "C" void kernel_launch(void* const* d_in, const int* in_sizes, int n_in,
                              void* d_out, int out_size) {
    const float* hs = (const float*)d_in[0];
    const float* w[4] = {(const float*)d_in[2], (const float*)d_in[6],
                         (const float*)d_in[10], (const float*)d_in[14]};
    const float* bias[4] = {(const float*)d_in[3], (const float*)d_in[7],
                            (const float*)d_in[11], (const float*)d_in[15]};
    const float* l1[4] = {(const float*)d_in[4], (const float*)d_in[8],
                          (const float*)d_in[12], (const float*)d_in[16]};
    const float* l2[4] = {(const float*)d_in[5], (const float*)d_in[9],
                          (const float*)d_in[13], (const float*)d_in[17]};

    float *Ub, *rowA;
    __nv_bfloat16 *Whp, *Wlp, *Xhp, *Xlp;
    __half *Qh, *Ql, *Kh, *Kl, *Vh, *Vl;
    cudaGetSymbolAddress((void**)&Ub, g_U);
    cudaGetSymbolAddress((void**)&rowA, g_rowAlive);
    cudaGetSymbolAddress((void**)&Whp, g_Wh);
    cudaGetSymbolAddress((void**)&Wlp, g_Wl);
    cudaGetSymbolAddress((void**)&Xhp, g_Xh);
    cudaGetSymbolAddress((void**)&Xlp, g_Xl);
    cudaGetSymbolAddress((void**)&Qh, g_Qh);
    cudaGetSymbolAddress((void**)&Ql, g_Ql);
    cudaGetSymbolAddress((void**)&Kh, g_Kh);
    cudaGetSymbolAddress((void**)&Kl, g_Kl);
    cudaGetSymbolAddress((void**)&Vh, g_Vh);
    cudaGetSymbolAddress((void**)&Vl, g_Vl);

    cudaFuncSetAttribute(qkv_hmma, cudaFuncAttributeMaxDynamicSharedMemorySize,
                         GSMEM_TOTAL);
    cudaFuncSetAttribute(gemm_out, cudaFuncAttributeMaxDynamicSharedMemorySize,
                         GSMEM_TOTAL);
    cudaFuncSetAttribute(flash_hmma, cudaFuncAttributeMaxDynamicSharedMemorySize,
                         FSMEM);

    // 1) alive masks
    alive2_kernel<<<dim3(16, 4), 256>>>(w[0], w[1], w[2], w[3]);

    // 2) bf16 splits: all 4 weights in one launch + hidden states
    splitw_kernel<<<dim3(512, 4), 256>>>(w[0], w[1], w[2], w[3]);
    split_kernel<<<1024, 256>>>(hs, Xhp, Xlp, MTOT * EE / 4);

    // 3) LoRA U for q/k/v (fused)
    u3_kernel<<<MTOT, 256>>>(hs, l1[0], l1[1], l1[2]);

    // 4) Fused Q/K/V projections (Q pre-scaled by SCALING*LOG2E)
    QkvArgs qa;
    for (int p = 0; p < 3; p++) {
        qa.Wh[p] = Whp + (size_t)p * EE * EE;
        qa.Wl[p] = Wlp + (size_t)p * EE * EE;
        qa.bias[p] = bias[p];
        qa.U[p] = Ub + p * MTOT * RR;
        qa.L2[p] = l2[p];
        qa.alive[p] = rowA + p * EE;
    }
    qa.OutH[0] = (uint16_t*)Qh; qa.OutL[0] = (uint16_t*)Ql;
    qa.OutH[1] = (uint16_t*)Kh; qa.OutL[1] = (uint16_t*)Kl;
    qa.OutH[2] = (uint16_t*)Vh; qa.OutL[2] = (uint16_t*)Vl;
    qa.scale[0] = SCALING * LOG2E;
    qa.scale[1] = 1.0f;
    qa.scale[2] = 1.0f;
    qkv_hmma<<<dim3(EE / 128, MTOT / 128, 3), 256, GSMEM_TOTAL>>>(Xhp, Xlp, qa);

    // 5) Flash attention -> attn bf16 hi/lo into g_Xh/g_Xl
    flash_hmma<<<dim3(TT / 64, HH, BB), 128, FSMEM>>>();

    // 6) Output projection
    uo_kernel<<<MTOT, 256>>>(Xhp, Xlp, l1[3]);
    gemm_out<<<dim3(EE / 128, MTOT / 128), 256, GSMEM_TOTAL>>>(
        Xhp, Xlp, Whp + (size_t)3 * EE * EE, Wlp + (size_t)3 * EE * EE,
        bias[3], Ub + 3 * MTOT * RR, l2[3], rowA + 3 * EE, (float*)d_out);
}

// round 17
// speedup vs baseline: 1.5380x; 1.5380x over previous
#include <cuda_runtime.h>
#include <cuda_bf16.h>
#include <cuda_fp16.h>
#include <math.h>
#include <float.h>
#include <stdint.h>

// Problem constants
#define BB 2
#define TT 2048
#define EE 2048
#define HH 32
#define DD 64
#define RR 8
#define MTOT (BB * TT) /* 4096 */
#define SCALING 0.125f /* D^-0.5 */
#define LOG2E 1.4426950408889634f

// ---------------------------------------------------------------------------
// Scratch (device globals; no allocations allowed)
// ---------------------------------------------------------------------------
__device__ float g_U[4][MTOT * RR];
__device__ float g_colAlive[4][EE];
__device__ float g_rowAlive[4][EE];
// bf16 split operands
__device__ __nv_bfloat16 g_Wh[(size_t)4 * EE * EE];
__device__ __nv_bfloat16 g_Wl[(size_t)4 * EE * EE];
__device__ __nv_bfloat16 g_Xh[(size_t)MTOT * EE];   // hs split; later attn split
__device__ __nv_bfloat16 g_Xl[(size_t)MTOT * EE];
// Q/K bf16 hi/lo, V fp16 hi/lo, all [B,H,T,D]
__device__ __nv_bfloat16 g_Qh[(size_t)BB * HH * TT * DD];
__device__ __nv_bfloat16 g_Ql[(size_t)BB * HH * TT * DD];
__device__ __nv_bfloat16 g_Kh[(size_t)BB * HH * TT * DD];
__device__ __nv_bfloat16 g_Kl[(size_t)BB * HH * TT * DD];
__device__ __half g_Vh[(size_t)BB * HH * TT * DD];
__device__ __half g_Vl[(size_t)BB * HH * TT * DD];

// ---------------------------------------------------------------------------
// PTX helpers (sm_80+ ISA only — harness compiles at sm_103 base, no tcgen05)
// ---------------------------------------------------------------------------
__device__ __forceinline__ uint32_t smem_u32(const void* p) {
    uint32_t a;
    asm("{ .reg .u64 t; cvta.to.shared.u64 t, %1; cvt.u32.u64 %0, t; }"
        : "=r"(a) : "l"(p));
    return a;
}
__device__ __forceinline__ void cp_async16(uint32_t dst, const void* src) {
    asm volatile("cp.async.cg.shared.global [%0], [%1], 16;"
                 :: "r"(dst), "l"(src) : "memory");
}
#define CP_COMMIT() asm volatile("cp.async.commit_group;" ::: "memory")
#define CP_WAIT1()  asm volatile("cp.async.wait_group 1;" ::: "memory")
#define CP_WAIT0()  asm volatile("cp.async.wait_group 0;" ::: "memory")

__device__ __forceinline__ void ldsm_x4(uint32_t r[4], uint32_t addr) {
    asm volatile("ldmatrix.sync.aligned.m8n8.x4.shared.b16 {%0,%1,%2,%3}, [%4];"
                 : "=r"(r[0]), "=r"(r[1]), "=r"(r[2]), "=r"(r[3]) : "r"(addr));
}
__device__ __forceinline__ void ldsm_t4(uint32_t r[4], uint32_t addr) {
    asm volatile("ldmatrix.sync.aligned.m8n8.x4.trans.shared.b16 {%0,%1,%2,%3}, [%4];"
                 : "=r"(r[0]), "=r"(r[1]), "=r"(r[2]), "=r"(r[3]) : "r"(addr));
}
__device__ __forceinline__ void mma16816(float c[4], const uint32_t a[4],
                                         uint32_t b0, uint32_t b1) {
    asm volatile(
        "mma.sync.aligned.m16n8k16.row.col.f32.bf16.bf16.f32 "
        "{%0,%1,%2,%3}, {%4,%5,%6,%7}, {%8,%9}, {%0,%1,%2,%3};"
        : "+f"(c[0]), "+f"(c[1]), "+f"(c[2]), "+f"(c[3])
        : "r"(a[0]), "r"(a[1]), "r"(a[2]), "r"(a[3]), "r"(b0), "r"(b1));
}
__device__ __forceinline__ void mma16816h(float c[4], const uint32_t a[4],
                                          uint32_t b0, uint32_t b1) {
    asm volatile(
        "mma.sync.aligned.m16n8k16.row.col.f32.f16.f16.f32 "
        "{%0,%1,%2,%3}, {%4,%5,%6,%7}, {%8,%9}, {%0,%1,%2,%3};"
        : "+f"(c[0]), "+f"(c[1]), "+f"(c[2]), "+f"(c[3])
        : "r"(a[0]), "r"(a[1]), "r"(a[2]), "r"(a[3]), "r"(b0), "r"(b1));
}
__device__ __forceinline__ uint32_t swz(uint32_t off) {
    return off ^ ((off >> 3) & 0x70);
}
__device__ __forceinline__ uint32_t packbf(float a, float b) {
    union { __nv_bfloat16 h[2]; uint32_t u; } t;
    t.h[0] = __float2bfloat16(a);
    t.h[1] = __float2bfloat16(b);
    return t.u;
}
__device__ __forceinline__ uint32_t packres(float a, float b, uint32_t hp) {
    union { __nv_bfloat16 h[2]; uint32_t u; } t;
    t.u = hp;
    return packbf(a - __bfloat162float(t.h[0]), b - __bfloat162float(t.h[1]));
}
// fp16 pack: a -> low half, b -> high half
__device__ __forceinline__ uint32_t packh(float a, float b) {
    uint32_t d;
    asm("cvt.rn.f16x2.f32 %0, %1, %2;" : "=r"(d) : "f"(b), "f"(a));
    return d;
}
__device__ __forceinline__ uint32_t packhres(float a, float b, uint32_t hp) {
    __half2 h = *reinterpret_cast<const __half2*>(&hp);
    return packh(a - __low2float(h), b - __high2float(h));
}
__device__ __forceinline__ uint32_t exp2h2(uint32_t y) {
    uint32_t p;
    asm volatile("ex2.approx.f16x2 %0, %1;" : "=r"(p) : "r"(y));
    return p;
}
__device__ __forceinline__ float exp2f32(float x) {
    float r;
    asm volatile("ex2.approx.f32 %0, %1;" : "=f"(r) : "f"(x));
    return r;
}
#define ONES_H2 0x3C003C00u

// ---------------------------------------------------------------------------
// Weight-mask ("alive") — early-exit scans
// ---------------------------------------------------------------------------
__global__ void alive2_kernel(const float* __restrict__ w0, const float* __restrict__ w1,
                              const float* __restrict__ w2, const float* __restrict__ w3) {
    const float* ws[4] = {w0, w1, w2, w3};
    const int p = blockIdx.y;
    const float* w = ws[p];
    const int idx = blockIdx.x * 256 + threadIdx.x;
    if (idx < EE) {
        float a = 0.0f;
        for (int i = 0; i < EE; i++)
            if (w[(size_t)i * EE + idx] != 0.0f) { a = 1.0f; break; }
        g_colAlive[p][idx] = a;
    } else {
        const int r = idx - EE;
        const float* row = w + (size_t)r * EE;
        float a = 0.0f;
        for (int j = 0; j < EE; j++)
            if (row[j] != 0.0f) { a = 1.0f; break; }
        g_rowAlive[p][r] = a;
    }
}

// ---------------------------------------------------------------------------
// fp32 -> (bf16 hi, bf16 lo) splits
// ---------------------------------------------------------------------------
__device__ __forceinline__ void split4(const float* __restrict__ src,
                                       __nv_bfloat16* __restrict__ hi,
                                       __nv_bfloat16* __restrict__ lo, int i) {
    float4 v = ((const float4*)src)[i];
    union { __nv_bfloat16 b[4]; uint2 u; } H, L;
    H.b[0] = __float2bfloat16(v.x);
    H.b[1] = __float2bfloat16(v.y);
    H.b[2] = __float2bfloat16(v.z);
    H.b[3] = __float2bfloat16(v.w);
    L.b[0] = __float2bfloat16(v.x - __bfloat162float(H.b[0]));
    L.b[1] = __float2bfloat16(v.y - __bfloat162float(H.b[1]));
    L.b[2] = __float2bfloat16(v.z - __bfloat162float(H.b[2]));
    L.b[3] = __float2bfloat16(v.w - __bfloat162float(H.b[3]));
    ((uint2*)hi)[i] = H.u;
    ((uint2*)lo)[i] = L.u;
}

// all 4 weights in one launch (blockIdx.y selects projection)
__global__ void splitw_kernel(const float* __restrict__ w0, const float* __restrict__ w1,
                              const float* __restrict__ w2, const float* __restrict__ w3) {
    const float* ws[4] = {w0, w1, w2, w3};
    const int p = blockIdx.y;
    const float* src = ws[p];
    __nv_bfloat16* hi = g_Wh + (size_t)p * EE * EE;
    __nv_bfloat16* lo = g_Wl + (size_t)p * EE * EE;
    const int n4 = EE * EE / 4;
    const int stride = gridDim.x * blockDim.x;
    for (int i = blockIdx.x * blockDim.x + threadIdx.x; i < n4; i += stride)
        split4(src, hi, lo, i);
}

__global__ void split_kernel(const float* __restrict__ src,
                             __nv_bfloat16* __restrict__ hi,
                             __nv_bfloat16* __restrict__ lo, int n4) {
    const int stride = gridDim.x * blockDim.x;
    for (int i = blockIdx.x * blockDim.x + threadIdx.x; i < n4; i += stride)
        split4(src, hi, lo, i);
}

// ---------------------------------------------------------------------------
// LoRA U kernels
// ---------------------------------------------------------------------------
__global__ __launch_bounds__(256) void u3_kernel(const float* __restrict__ X,
                                                 const float* __restrict__ L1a,
                                                 const float* __restrict__ L1b,
                                                 const float* __restrict__ L1c) {
    const int m = blockIdx.x;
    const int tid = threadIdx.x;
    float acc[3][RR];
#pragma unroll
    for (int p = 0; p < 3; p++)
#pragma unroll
        for (int r = 0; r < RR; r++) acc[p][r] = 0.0f;

    const float* Xr = X + (size_t)m * EE;
    for (int e = tid; e < EE; e += 256) {
        const float x = Xr[e];
        const float x0 = x * g_colAlive[0][e];
        const float x1 = x * g_colAlive[1][e];
        const float x2 = x * g_colAlive[2][e];
#pragma unroll
        for (int r = 0; r < RR; r++) {
            acc[0][r] = fmaf(x0, L1a[r * EE + e], acc[0][r]);
            acc[1][r] = fmaf(x1, L1b[r * EE + e], acc[1][r]);
            acc[2][r] = fmaf(x2, L1c[r * EE + e], acc[2][r]);
        }
    }
#pragma unroll
    for (int p = 0; p < 3; p++)
#pragma unroll
        for (int r = 0; r < RR; r++)
            for (int off = 16; off; off >>= 1)
                acc[p][r] += __shfl_xor_sync(0xffffffffu, acc[p][r], off);

    __shared__ float red[8][24];
    if ((tid & 31) == 0) {
        int w = tid >> 5;
#pragma unroll
        for (int p = 0; p < 3; p++)
#pragma unroll
            for (int r = 0; r < RR; r++) red[w][p * RR + r] = acc[p][r];
    }
    __syncthreads();
    if (tid < 24) {
        float s = 0.0f;
#pragma unroll
        for (int w = 0; w < 8; w++) s += red[w][tid];
        g_U[tid >> 3][m * RR + (tid & 7)] = s;
    }
}

__global__ __launch_bounds__(256) void uo_kernel(const __nv_bfloat16* __restrict__ Xh,
                                                 const __nv_bfloat16* __restrict__ Xl,
                                                 const float* __restrict__ L1) {
    const int m = blockIdx.x;
    const int tid = threadIdx.x;
    const float* ca = g_colAlive[3];
    float acc[RR];
#pragma unroll
    for (int r = 0; r < RR; r++) acc[r] = 0.0f;

    const __nv_bfloat16* Xhr = Xh + (size_t)m * EE;
    const __nv_bfloat16* Xlr = Xl + (size_t)m * EE;
    for (int e = tid; e < EE; e += 256) {
        float xv = (__bfloat162float(Xhr[e]) + __bfloat162float(Xlr[e])) * ca[e];
#pragma unroll
        for (int r = 0; r < RR; r++) acc[r] = fmaf(xv, L1[r * EE + e], acc[r]);
    }
#pragma unroll
    for (int r = 0; r < RR; r++)
        for (int off = 16; off; off >>= 1)
            acc[r] += __shfl_xor_sync(0xffffffffu, acc[r], off);

    __shared__ float red[8][RR];
    if ((tid & 31) == 0) {
        int w = tid >> 5;
#pragma unroll
        for (int r = 0; r < RR; r++) red[w][r] = acc[r];
    }
    __syncthreads();
    if (tid < RR) {
        float s = 0.0f;
#pragma unroll
        for (int w = 0; w < 8; w++) s += red[w][tid];
        g_U[3][m * RR + tid] = s;
    }
}

// ---------------------------------------------------------------------------
// Shared HMMA bf16-split GEMM core (Ah*Wh + Ah*Wl + Al*Wh)
// ---------------------------------------------------------------------------
#define STAGE_BYTES 65536
#define AH_OFF 0
#define AL_OFF 16384
#define WH_OFF 32768
#define WL_OFF 49152
#define GSMEM_TOTAL (2 * STAGE_BYTES)
#define NCHUNK (EE / 64)

__device__ __forceinline__ void stage_load(char* dst,
                                           const __nv_bfloat16* __restrict__ Ah,
                                           const __nv_bfloat16* __restrict__ Al,
                                           const __nv_bfloat16* __restrict__ Wh,
                                           const __nv_bfloat16* __restrict__ Wl,
                                           int m0, int n0, int k0, int tid) {
    const uint32_t dbase = smem_u32(dst);
#pragma unroll
    for (int i = 0; i < 4; i++) {
        int u = tid + i * 256;
        int row = u >> 3, c = u & 7;
        uint32_t so = swz((uint32_t)(row * 128 + c * 16));
        size_t goA = (size_t)(m0 + row) * EE + k0 + c * 8;
        size_t goW = (size_t)(n0 + row) * EE + k0 + c * 8;
        cp_async16(dbase + AH_OFF + so, Ah + goA);
        cp_async16(dbase + AL_OFF + so, Al + goA);
        cp_async16(dbase + WH_OFF + so, Wh + goW);
        cp_async16(dbase + WL_OFF + so, Wl + goW);
    }
}

__device__ __forceinline__ void gemm_core(float acc[4][4][4],
                                          const __nv_bfloat16* __restrict__ Ah,
                                          const __nv_bfloat16* __restrict__ Al,
                                          const __nv_bfloat16* __restrict__ Wh,
                                          const __nv_bfloat16* __restrict__ Wl,
                                          int m0, int n0, char* smem) {
    const int tid = threadIdx.x;
    const int wid = tid >> 5;
    const int lane = tid & 31;
    const int wm = wid & 1;
    const int wn = wid >> 1;
    const int arow = lane & 15;
    const int acolb = (lane >> 4) << 4;
    const int brow = (lane & 7) + ((lane >> 4) << 3);
    const int bcolb = ((lane >> 3) & 1) << 4;

    stage_load(smem, Ah, Al, Wh, Wl, m0, n0, 0, tid);
    CP_COMMIT();

    for (int ch = 0; ch < NCHUNK; ch++) {
        const int s = ch & 1;
        if (ch + 1 < NCHUNK) {
            stage_load(smem + (s ^ 1) * STAGE_BYTES, Ah, Al, Wh, Wl,
                       m0, n0, (ch + 1) * 64, tid);
            CP_COMMIT();
            CP_WAIT1();
        } else {
            CP_WAIT0();
        }
        __syncthreads();

        const uint32_t sb = smem_u32(smem + s * STAGE_BYTES);
#pragma unroll
        for (int kk = 0; kk < 4; kk++) {
            const int kB = kk * 32;
            uint32_t ah[4][4], al[4][4], bh[2][4], bl[2][4];
#pragma unroll
            for (int fm = 0; fm < 4; fm++) {
                uint32_t so = swz((uint32_t)((wm * 64 + fm * 16 + arow) * 128 + kB + acolb));
                ldsm_x4(ah[fm], sb + AH_OFF + so);
                ldsm_x4(al[fm], sb + AL_OFF + so);
            }
#pragma unroll
            for (int g = 0; g < 2; g++) {
                uint32_t so = swz((uint32_t)((wn * 32 + g * 16 + brow) * 128 + kB + bcolb));
                ldsm_x4(bh[g], sb + WH_OFF + so);
                ldsm_x4(bl[g], sb + WL_OFF + so);
            }
#pragma unroll
            for (int fm = 0; fm < 4; fm++)
#pragma unroll
                for (int fn = 0; fn < 4; fn++) {
                    const int g = fn >> 1, p = (fn & 1) << 1;
                    mma16816(acc[fm][fn], ah[fm], bh[g][p], bh[g][p + 1]);
                    mma16816(acc[fm][fn], ah[fm], bl[g][p], bl[g][p + 1]);
                    mma16816(acc[fm][fn], al[fm], bh[g][p], bh[g][p + 1]);
                }
        }
        __syncthreads();
    }
}

// ---------------------------------------------------------------------------
// Fused QKV GEMM: grid.z selects projection. Q/K -> bf16 hi/lo head layout,
// V -> fp16 hi/lo head layout. Q pre-scaled by SCALING*LOG2E.
// ---------------------------------------------------------------------------
struct QkvArgs {
    const __nv_bfloat16* Wh[3];
    const __nv_bfloat16* Wl[3];
    const float* bias[3];
    const float* U[3];
    const float* L2[3];
    const float* alive[3];
    uint16_t* OutH[3];
    uint16_t* OutL[3];
    float scale[3];
};

__global__ __launch_bounds__(256, 1) void qkv_hmma(
    const __nv_bfloat16* __restrict__ Ah, const __nv_bfloat16* __restrict__ Al,
    QkvArgs args) {
    extern __shared__ char smem[];
    const int z = blockIdx.z;
    const int m0 = blockIdx.y * 128;
    const int n0 = blockIdx.x * 128;
    const int tid = threadIdx.x;
    const int wid = tid >> 5;
    const int lane = tid & 31;
    const int wm = wid & 1;
    const int wn = wid >> 1;
    const bool halfOut = (z == 2);

    float acc[4][4][4];
#pragma unroll
    for (int a = 0; a < 4; a++)
#pragma unroll
        for (int b = 0; b < 4; b++)
#pragma unroll
            for (int c = 0; c < 4; c++) acc[a][b][c] = 0.0f;

    gemm_core(acc, Ah, Al, args.Wh[z], args.Wl[z], m0, n0, smem);

    const float* bias = args.bias[z];
    const float* U = args.U[z];
    const float* L2 = args.L2[z];
    const float* alive = args.alive[z];
    uint16_t* OutH = args.OutH[z];
    uint16_t* OutL = args.OutL[z];
    const float scale = args.scale[z];

#pragma unroll
    for (int fm = 0; fm < 4; fm++) {
        const int mlo = m0 + wm * 64 + fm * 16 + (lane >> 2);
        const int mhi = mlo + 8;
        float ulo[RR], uhi[RR];
#pragma unroll
        for (int r = 0; r < RR; r++) {
            ulo[r] = U[mlo * RR + r];
            uhi[r] = U[mhi * RR + r];
        }
#pragma unroll
        for (int fn = 0; fn < 4; fn++) {
            const int n = n0 + wn * 32 + fn * 8 + ((lane & 3) << 1);
            float out[4];
#pragma unroll
            for (int jj = 0; jj < 2; jj++) {
                const int nn = n + jj;
                const float av = alive[nn];
                float lo = acc[fm][fn][jj] + bias[nn];
                float hi = acc[fm][fn][2 + jj] + bias[nn];
#pragma unroll
                for (int r = 0; r < RR; r++) {
                    const float lv = L2[nn * RR + r] * av;
                    lo = fmaf(ulo[r], lv, lo);
                    hi = fmaf(uhi[r], lv, hi);
                }
                out[jj] = lo * scale;
                out[2 + jj] = hi * scale;
            }
            const int h = n >> 6, d0 = n & 63;
            const int blo = mlo >> 11, tlo = mlo & (TT - 1);
            const int bhi = mhi >> 11, thi = mhi & (TT - 1);
            size_t off_lo = ((size_t)(blo * HH + h) * TT + tlo) * DD + d0;
            size_t off_hi = ((size_t)(bhi * HH + h) * TT + thi) * DD + d0;
            uint32_t hp0, lp0, hp1, lp1;
            if (halfOut) {
                hp0 = packh(out[0], out[1]);
                lp0 = packhres(out[0], out[1], hp0);
                hp1 = packh(out[2], out[3]);
                lp1 = packhres(out[2], out[3], hp1);
            } else {
                hp0 = packbf(out[0], out[1]);
                lp0 = packres(out[0], out[1], hp0);
                hp1 = packbf(out[2], out[3]);
                lp1 = packres(out[2], out[3], hp1);
            }
            *(uint32_t*)(OutH + off_lo) = hp0;
            *(uint32_t*)(OutL + off_lo) = lp0;
            *(uint32_t*)(OutH + off_hi) = hp1;
            *(uint32_t*)(OutL + off_hi) = lp1;
        }
    }
}

// ---------------------------------------------------------------------------
// O-projection GEMM (fp32 out, [M,E])
// ---------------------------------------------------------------------------
__global__ __launch_bounds__(256, 1) void gemm_out(
    const __nv_bfloat16* __restrict__ Ah, const __nv_bfloat16* __restrict__ Al,
    const __nv_bfloat16* __restrict__ Wh, const __nv_bfloat16* __restrict__ Wl,
    const float* __restrict__ bias, const float* __restrict__ U,
    const float* __restrict__ L2, const float* __restrict__ rowAlive,
    float* __restrict__ Cout) {
    extern __shared__ char smem[];
    const int tid = threadIdx.x;
    const int wid = tid >> 5;
    const int lane = tid & 31;
    const int wm = wid & 1;
    const int wn = wid >> 1;
    const int m0 = blockIdx.y * 128;
    const int n0 = blockIdx.x * 128;

    float acc[4][4][4];
#pragma unroll
    for (int a = 0; a < 4; a++)
#pragma unroll
        for (int b = 0; b < 4; b++)
#pragma unroll
            for (int c = 0; c < 4; c++) acc[a][b][c] = 0.0f;

    gemm_core(acc, Ah, Al, Wh, Wl, m0, n0, smem);

#pragma unroll
    for (int fm = 0; fm < 4; fm++) {
        const int mlo = m0 + wm * 64 + fm * 16 + (lane >> 2);
        const int mhi = mlo + 8;
        float ulo[RR], uhi[RR];
#pragma unroll
        for (int r = 0; r < RR; r++) {
            ulo[r] = U[mlo * RR + r];
            uhi[r] = U[mhi * RR + r];
        }
#pragma unroll
        for (int fn = 0; fn < 4; fn++) {
            const int n = n0 + wn * 32 + fn * 8 + ((lane & 3) << 1);
            float out[4];
#pragma unroll
            for (int jj = 0; jj < 2; jj++) {
                const int nn = n + jj;
                const float av = rowAlive[nn];
                float lo = acc[fm][fn][jj] + bias[nn];
                float hi = acc[fm][fn][2 + jj] + bias[nn];
#pragma unroll
                for (int r = 0; r < RR; r++) {
                    const float lv = L2[nn * RR + r] * av;
                    lo = fmaf(ulo[r], lv, lo);
                    hi = fmaf(uhi[r], lv, hi);
                }
                out[jj] = lo;
                out[2 + jj] = hi;
            }
            *(float2*)(Cout + (size_t)mlo * EE + n) = make_float2(out[0], out[1]);
            *(float2*)(Cout + (size_t)mhi * EE + n) = make_float2(out[2], out[3]);
        }
    }
}

// ---------------------------------------------------------------------------
// Flash attention: bf16 3-pass QK^T (log2 domain, Q pre-scaled),
// packed ex2.approx.f16x2 softmax, fp16 P, fp16-split 2-pass PV,
// row-sums via MMA with all-ones B. 128 threads, 2 CTAs/SM.
// (Exact configuration of the 1410us winner.)
// ---------------------------------------------------------------------------
#define FQ_H 0
#define FQ_L 8192
#define FSTG 16384
#define FK_H 0
#define FK_L 8192
#define FV_H 16384
#define FV_L 24576
#define FSTG_SZ 32768
#define FSMEM (16384 + 2 * FSTG_SZ)   /* 81920 */

__device__ __forceinline__ void f_load_tile(uint32_t dstb,
                                            const uint16_t* __restrict__ src,
                                            int tid) {
#pragma unroll
    for (int i = 0; i < 4; i++) {
        int u = tid + i * 128;
        int r = u >> 3, c = u & 7;
        cp_async16(dstb + swz((uint32_t)(r * 128 + c * 16)), src + r * 64 + c * 8);
    }
}

__global__ __launch_bounds__(128, 2) void flash_hmma() {
    const int qb = (TT / 64 - 1) - blockIdx.x;
    const int h = blockIdx.y;
    const int b = blockIdx.z;
    const int t0 = qb * 64;
    const size_t ho = (size_t)(b * HH + h) * TT * DD;

    extern __shared__ char smem[];
    const uint32_t sbase = smem_u32(smem);
    const int tid = threadIdx.x, wid = tid >> 5, lane = tid & 31;
    const int rq = lane >> 2, cq = lane & 3;

    f_load_tile(sbase + FQ_H, (const uint16_t*)(g_Qh + ho + (size_t)t0 * DD), tid);
    f_load_tile(sbase + FQ_L, (const uint16_t*)(g_Ql + ho + (size_t)t0 * DD), tid);
    f_load_tile(sbase + FSTG + FK_H, (const uint16_t*)(g_Kh + ho), tid);
    f_load_tile(sbase + FSTG + FK_L, (const uint16_t*)(g_Kl + ho), tid);
    f_load_tile(sbase + FSTG + FV_H, (const uint16_t*)(g_Vh + ho), tid);
    f_load_tile(sbase + FSTG + FV_L, (const uint16_t*)(g_Vl + ho), tid);
    CP_COMMIT();

    float oacc[8][4];
#pragma unroll
    for (int f = 0; f < 8; f++)
#pragma unroll
        for (int j = 0; j < 4; j++) oacc[f][j] = 0.0f;
    float m0 = -1e30f, m1 = -1e30f, l0 = 0.0f, l1 = 0.0f;

    const int arow = lane & 15;
    const int acolb = (lane >> 4) << 4;
    const int brow = (lane & 7) + ((lane >> 4) << 3);
    const int bcolb = ((lane >> 3) & 1) << 4;

    for (int kb = 0; kb <= qb; kb++) {
        const int s = kb & 1;
        if (kb < qb) {
            const uint32_t nb = sbase + FSTG + (s ^ 1) * FSTG_SZ;
            const size_t so = (size_t)(kb + 1) * 64 * DD;
            f_load_tile(nb + FK_H, (const uint16_t*)(g_Kh + ho + so), tid);
            f_load_tile(nb + FK_L, (const uint16_t*)(g_Kl + ho + so), tid);
            f_load_tile(nb + FV_H, (const uint16_t*)(g_Vh + ho + so), tid);
            f_load_tile(nb + FV_L, (const uint16_t*)(g_Vl + ho + so), tid);
            CP_COMMIT();
            CP_WAIT1();
        } else {
            CP_WAIT0();
        }
        __syncthreads();

        const uint32_t kvb = sbase + FSTG + s * FSTG_SZ;
        float sacc[8][4];
#pragma unroll
        for (int f = 0; f < 8; f++)
#pragma unroll
            for (int j = 0; j < 4; j++) sacc[f][j] = 0.0f;

        // S' = (Q*scale*log2e) K^T  (bf16 3-pass)
#pragma unroll
        for (int kk = 0; kk < 4; kk++) {
            const int kB = kk * 32;
            uint32_t qh4[4], ql4[4];
            uint32_t qoff = swz((uint32_t)((wid * 16 + arow) * 128 + kB + acolb));
            ldsm_x4(qh4, sbase + FQ_H + qoff);
            ldsm_x4(ql4, sbase + FQ_L + qoff);
            uint32_t kh4[4][4], kl4[4][4];
#pragma unroll
            for (int g = 0; g < 4; g++) {
                uint32_t koff = swz((uint32_t)((g * 16 + brow) * 128 + kB + bcolb));
                ldsm_x4(kh4[g], kvb + FK_H + koff);
                ldsm_x4(kl4[g], kvb + FK_L + koff);
            }
#pragma unroll
            for (int fn = 0; fn < 8; fn++) {
                const int g = fn >> 1, p = (fn & 1) << 1;
                mma16816(sacc[fn], qh4, kh4[g][p], kh4[g][p + 1]);
                mma16816(sacc[fn], qh4, kl4[g][p], kl4[g][p + 1]);
                mma16816(sacc[fn], ql4, kh4[g][p], kh4[g][p + 1]);
            }
        }

        if (kb == qb) {
            const int rlo = wid * 16 + rq, rhi = rlo + 8;
#pragma unroll
            for (int fn = 0; fn < 8; fn++) {
                const int col = fn * 8 + 2 * cq;
                if (col > rlo) sacc[fn][0] = -FLT_MAX;
                if (col + 1 > rlo) sacc[fn][1] = -FLT_MAX;
                if (col > rhi) sacc[fn][2] = -FLT_MAX;
                if (col + 1 > rhi) sacc[fn][3] = -FLT_MAX;
            }
        }

        // row max (log2 domain)
        float mx0 = -FLT_MAX, mx1 = -FLT_MAX;
#pragma unroll
        for (int fn = 0; fn < 8; fn++) {
            mx0 = fmaxf(mx0, fmaxf(sacc[fn][0], sacc[fn][1]));
            mx1 = fmaxf(mx1, fmaxf(sacc[fn][2], sacc[fn][3]));
        }
        mx0 = fmaxf(mx0, __shfl_xor_sync(0xffffffffu, mx0, 1));
        mx0 = fmaxf(mx0, __shfl_xor_sync(0xffffffffu, mx0, 2));
        mx1 = fmaxf(mx1, __shfl_xor_sync(0xffffffffu, mx1, 1));
        mx1 = fmaxf(mx1, __shfl_xor_sync(0xffffffffu, mx1, 2));
        const float nm0 = fmaxf(m0, mx0), nm1 = fmaxf(m1, mx1);
        const float c0 = exp2f32(m0 - nm0), c1 = exp2f32(m1 - nm1);
        m0 = nm0;
        m1 = nm1;

        // packed exp2 -> fp16 P frags
        uint32_t pf[4][4];
#pragma unroll
        for (int kk = 0; kk < 4; kk++) {
#pragma unroll
            for (int q = 0; q < 2; q++) {
                const int fn = 2 * kk + q;
                pf[kk][2 * q + 0] =
                    exp2h2(packh(sacc[fn][0] - nm0, sacc[fn][1] - nm0));
                pf[kk][2 * q + 1] =
                    exp2h2(packh(sacc[fn][2] - nm1, sacc[fn][3] - nm1));
            }
        }

        // row sums via MMA with all-ones B
        float lacc[4] = {0.0f, 0.0f, 0.0f, 0.0f};
#pragma unroll
        for (int kk = 0; kk < 4; kk++)
            mma16816h(lacc, pf[kk], ONES_H2, ONES_H2);
        l0 = l0 * c0 + lacc[0];
        l1 = l1 * c1 + lacc[2];
#pragma unroll
        for (int fn = 0; fn < 8; fn++) {
            oacc[fn][0] *= c0;
            oacc[fn][1] *= c0;
            oacc[fn][2] *= c1;
            oacc[fn][3] *= c1;
        }

        // O += P V (fp16, 2-pass split); V via trans ldmatrix
#pragma unroll
        for (int kk = 0; kk < 4; kk++) {
            const int vrow = kk * 16 + (lane & 15);
            const int vcolb = (lane >> 4) << 4;
            uint32_t vh4[4][4], vl4[4][4];
#pragma unroll
            for (int g = 0; g < 4; g++) {
                uint32_t voff = swz((uint32_t)(vrow * 128 + g * 32 + vcolb));
                ldsm_t4(vh4[g], kvb + FV_H + voff);
                ldsm_t4(vl4[g], kvb + FV_L + voff);
            }
#pragma unroll
            for (int fn = 0; fn < 8; fn++) {
                const int g = fn >> 1, p = (fn & 1) << 1;
                mma16816h(oacc[fn], pf[kk], vh4[g][p], vh4[g][p + 1]);
                mma16816h(oacc[fn], pf[kk], vl4[g][p], vl4[g][p + 1]);
            }
        }
        __syncthreads();
    }

    // Epilogue: normalize, split to bf16 hi/lo, write [B*T, E]
    const float i0 = 1.0f / l0, i1 = 1.0f / l1;
    const int tlo = t0 + wid * 16 + rq, thi = tlo + 8;
    const size_t rlo = ((size_t)(b * TT) + tlo) * EE + h * DD;
    const size_t rhi = ((size_t)(b * TT) + thi) * EE + h * DD;
#pragma unroll
    for (int fn = 0; fn < 8; fn++) {
        const int e = fn * 8 + 2 * cq;
        float v0 = oacc[fn][0] * i0, v1 = oacc[fn][1] * i0;
        float v2 = oacc[fn][2] * i1, v3 = oacc[fn][3] * i1;
        uint32_t hp0 = packbf(v0, v1);
        uint32_t hp1 = packbf(v2, v3);
        *(uint32_t*)(g_Xh + rlo + e) = hp0;
        *(uint32_t*)(g_Xl + rlo + e) = packres(v0, v1, hp0);
        *(uint32_t*)(g_Xh + rhi + e) = hp1;
        *(uint32_t*)(g_Xl + rhi + e) = packres(v2, v3, hp1);
    }
}

// ---------------------------------------------------------------------------
// Launch
// ---------------------------------------------------------------------------
extern "C" void kernel_launch(void* const* d_in, const int* in_sizes, int n_in,
                              void* d_out, int out_size) {
    const float* hs = (const float*)d_in[0];
    const float* w[4] = {(const float*)d_in[2], (const float*)d_in[6],
                         (const float*)d_in[10], (const float*)d_in[14]};
    const float* bias[4] = {(const float*)d_in[3], (const float*)d_in[7],
                            (const float*)d_in[11], (const float*)d_in[15]};
    const float* l1[4] = {(const float*)d_in[4], (const float*)d_in[8],
                          (const float*)d_in[12], (const float*)d_in[16]};
    const float* l2[4] = {(const float*)d_in[5], (const float*)d_in[9],
                          (const float*)d_in[13], (const float*)d_in[17]};

    float *Ub, *rowA;
    __nv_bfloat16 *Whp, *Wlp, *Xhp, *Xlp, *Qh, *Ql, *Kh, *Kl;
    __half *Vh, *Vl;
    cudaGetSymbolAddress((void**)&Ub, g_U);
    cudaGetSymbolAddress((void**)&rowA, g_rowAlive);
    cudaGetSymbolAddress((void**)&Whp, g_Wh);
    cudaGetSymbolAddress((void**)&Wlp, g_Wl);
    cudaGetSymbolAddress((void**)&Xhp, g_Xh);
    cudaGetSymbolAddress((void**)&Xlp, g_Xl);
    cudaGetSymbolAddress((void**)&Qh, g_Qh);
    cudaGetSymbolAddress((void**)&Ql, g_Ql);
    cudaGetSymbolAddress((void**)&Kh, g_Kh);
    cudaGetSymbolAddress((void**)&Kl, g_Kl);
    cudaGetSymbolAddress((void**)&Vh, g_Vh);
    cudaGetSymbolAddress((void**)&Vl, g_Vl);

    cudaFuncSetAttribute(qkv_hmma, cudaFuncAttributeMaxDynamicSharedMemorySize,
                         GSMEM_TOTAL);
    cudaFuncSetAttribute(gemm_out, cudaFuncAttributeMaxDynamicSharedMemorySize,
                         GSMEM_TOTAL);
    cudaFuncSetAttribute(flash_hmma, cudaFuncAttributeMaxDynamicSharedMemorySize,
                         FSMEM);

    // 1) alive masks
    alive2_kernel<<<dim3(16, 4), 256>>>(w[0], w[1], w[2], w[3]);

    // 2) bf16 splits: all 4 weights in one launch + hidden states
    splitw_kernel<<<dim3(512, 4), 256>>>(w[0], w[1], w[2], w[3]);
    split_kernel<<<1024, 256>>>(hs, Xhp, Xlp, MTOT * EE / 4);

    // 3) LoRA U for q/k/v (fused)
    u3_kernel<<<MTOT, 256>>>(hs, l1[0], l1[1], l1[2]);

    // 4) Fused Q/K/V projections (Q pre-scaled by SCALING*LOG2E)
    QkvArgs qa;
    for (int p = 0; p < 3; p++) {
        qa.Wh[p] = Whp + (size_t)p * EE * EE;
        qa.Wl[p] = Wlp + (size_t)p * EE * EE;
        qa.bias[p] = bias[p];
        qa.U[p] = Ub + p * MTOT * RR;
        qa.L2[p] = l2[p];
        qa.alive[p] = rowA + p * EE;
    }
    qa.OutH[0] = (uint16_t*)Qh; qa.OutL[0] = (uint16_t*)Ql;
    qa.OutH[1] = (uint16_t*)Kh; qa.OutL[1] = (uint16_t*)Kl;
    qa.OutH[2] = (uint16_t*)Vh; qa.OutL[2] = (uint16_t*)Vl;
    qa.scale[0] = SCALING * LOG2E;
    qa.scale[1] = 1.0f;
    qa.scale[2] = 1.0f;
    qkv_hmma<<<dim3(EE / 128, MTOT / 128, 3), 256, GSMEM_TOTAL>>>(Xhp, Xlp, qa);

    // 5) Flash attention -> attn bf16 hi/lo into g_Xh/g_Xl
    flash_hmma<<<dim3(TT / 64, HH, BB), 128, FSMEM>>>();

    // 6) Output projection
    uo_kernel<<<MTOT, 256>>>(Xhp, Xlp, l1[3]);
    gemm_out<<<dim3(EE / 128, MTOT / 128), 256, GSMEM_TOTAL>>>(
        Xhp, Xlp, Whp + (size_t)3 * EE * EE, Wlp + (size_t)3 * EE * EE,
        bias[3], Ub + 3 * MTOT * RR, l2[3], rowA + 3 * EE, (float*)d_out);
}